// round 8
// baseline (speedup 1.0000x reference)
#include <cuda_runtime.h>
#include <math.h>

static constexpr int B   = 16;
static constexpr int C   = 64;
static constexpr int HW  = 256 * 256;   // 65536
static constexpr int HW4 = HW / 4;      // 16384
static constexpr int PB  = 64;          // pool blocks per batch (HW4/256)

// Per-block partial sums: [B][PB][8]  (7 used: sum/sumsq x3 channels, cnt)
// No zeroing needed: pool overwrites every slot every launch.
__device__ float g_part[B * PB * 8];

// ---------------------------------------------------------------------------
// K1: channel pool (max/mean/min over C) + masked per-block partial sums.
// Grid: (PB, B). Each thread owns 4 consecutive pixels (float4).
// Compiler-scheduled channel loop (regs=32): measured 44.1us / 6281 GB/s,
// which equals the compulsory 277MB of traffic -> at the memory ceiling.
// (Explicit 8-wide load batching was tried in R7 and REGRESSED ~30% via
// cross-CTA L1tex-queue contention — do not front-batch loads here.)
// ---------------------------------------------------------------------------
__global__ __launch_bounds__(256) void pool_kernel(const float* __restrict__ x,
                                                   const int*   __restrict__ mask,
                                                   float*       __restrict__ out) {
    const int b   = blockIdx.y;
    const int idx = blockIdx.x * blockDim.x + threadIdx.x;  // float4 index in HW4

    const float4* xb = reinterpret_cast<const float4*>(x) + (size_t)b * C * HW4 + idx;

    float4 mx = make_float4(-INFINITY, -INFINITY, -INFINITY, -INFINITY);
    float4 mn = make_float4( INFINITY,  INFINITY,  INFINITY,  INFINITY);
    float4 sm = make_float4(0.f, 0.f, 0.f, 0.f);

#pragma unroll 8
    for (int c = 0; c < C; c++) {
        float4 t = xb[(size_t)c * HW4];
        mx.x = fmaxf(mx.x, t.x); mx.y = fmaxf(mx.y, t.y);
        mx.z = fmaxf(mx.z, t.z); mx.w = fmaxf(mx.w, t.w);
        mn.x = fminf(mn.x, t.x); mn.y = fminf(mn.y, t.y);
        mn.z = fminf(mn.z, t.z); mn.w = fminf(mn.w, t.w);
        sm.x += t.x; sm.y += t.y; sm.z += t.z; sm.w += t.w;
    }
    const float inv = 1.0f / (float)C;
    float4 me = make_float4(sm.x * inv, sm.y * inv, sm.z * inv, sm.w * inv);

    // Write pooled channels into out (scratch): [B, 3, HW] — stays in L2.
    float4* ob = reinterpret_cast<float4*>(out) + (size_t)b * 3 * HW4 + idx;
    ob[0]       = mx;
    ob[HW4]     = me;
    ob[2 * HW4] = mn;

    // Masked partial sums for this thread's 4 pixels.
    int4 mi = reinterpret_cast<const int4*>(mask)[b * HW4 + idx];
    float m0 = (mi.x == 1) ? 1.f : 0.f;
    float m1 = (mi.y == 1) ? 1.f : 0.f;
    float m2 = (mi.z == 1) ? 1.f : 0.f;
    float m3 = (mi.w == 1) ? 1.f : 0.f;

    float r[7];
    r[0] = mx.x * m0 + mx.y * m1 + mx.z * m2 + mx.w * m3;
    r[1] = mx.x * mx.x * m0 + mx.y * mx.y * m1 + mx.z * mx.z * m2 + mx.w * mx.w * m3;
    r[2] = me.x * m0 + me.y * m1 + me.z * m2 + me.w * m3;
    r[3] = me.x * me.x * m0 + me.y * me.y * m1 + me.z * me.z * m2 + me.w * me.w * m3;
    r[4] = mn.x * m0 + mn.y * m1 + mn.z * m2 + mn.w * m3;
    r[5] = mn.x * mn.x * m0 + mn.y * mn.y * m1 + mn.z * mn.z * m2 + mn.w * mn.w * m3;
    r[6] = m0 + m1 + m2 + m3;

    // Warp reduce
#pragma unroll
    for (int off = 16; off > 0; off >>= 1) {
#pragma unroll
        for (int k = 0; k < 7; k++)
            r[k] += __shfl_down_sync(0xffffffffu, r[k], off);
    }

    __shared__ float sh[7][8];
    int lane = threadIdx.x & 31;
    int w    = threadIdx.x >> 5;
    if (lane == 0) {
#pragma unroll
        for (int k = 0; k < 7; k++) sh[k][w] = r[k];
    }
    __syncthreads();

    if (w == 0) {
#pragma unroll
        for (int k = 0; k < 7; k++) r[k] = (lane < 8) ? sh[k][lane] : 0.f;
#pragma unroll
        for (int off = 4; off > 0; off >>= 1) {
#pragma unroll
            for (int k = 0; k < 7; k++)
                r[k] += __shfl_down_sync(0xffffffffu, r[k], off);
        }
        if (lane == 0) {
            float* p = &g_part[(b * PB + blockIdx.x) * 8];
#pragma unroll
            for (int k = 0; k < 7; k++) p[k] = r[k];
        }
    }
}

// ---------------------------------------------------------------------------
// K2: normalize in place: out = ((xc - mean) / std) * (mask==1)
// Main-data structure identical to the proven 7.3us R5 norm (1 float4/thread).
// Stats are computed INLINE per block: each block needs exactly one (b,ch)
// mean/istd; 64 threads reduce the 64 partial rows (L2-resident, double
// accumulation), overlapped with the block's own v/mi global loads.
// ---------------------------------------------------------------------------
__global__ __launch_bounds__(256) void norm_kernel(const int* __restrict__ mask,
                                                   float*     __restrict__ out) {
    const int e4  = blockIdx.x * blockDim.x + threadIdx.x;  // float4 index
    const int b3  = blockIdx.x >> 6;   // e4 >> 14, uniform per block
    const int hw4 = e4 & (HW4 - 1);
    const int b   = b3 / 3;
    const int ch  = b3 - b * 3;

    // Issue the long-latency main loads first; stats reduce overlaps them.
    float4 v  = reinterpret_cast<float4*>(out)[e4];
    int4   mi = reinterpret_cast<const int4*>(mask)[b * HW4 + hw4];

    // Inline stats: threads 0..63 each load one partial row's 3 values.
    __shared__ float s_mean, s_istd;
    __shared__ double sh_s[2], sh_ss[2], sh_c[2];
    const int t    = threadIdx.x;
    const int lane = t & 31;
    if (t < 64) {
        const float* p = &g_part[(b * PB + t) * 8];
        double s  = (double)p[ch * 2];
        double ss = (double)p[ch * 2 + 1];
        double cn = (double)p[6];
#pragma unroll
        for (int off = 16; off > 0; off >>= 1) {
            s  += __shfl_down_sync(0xffffffffu, s,  off);
            ss += __shfl_down_sync(0xffffffffu, ss, off);
            cn += __shfl_down_sync(0xffffffffu, cn, off);
        }
        if (lane == 0) { sh_s[t >> 5] = s; sh_ss[t >> 5] = ss; sh_c[t >> 5] = cn; }
    }
    __syncthreads();
    if (t == 0) {
        double s    = sh_s[0] + sh_s[1];
        double ss   = sh_ss[0] + sh_ss[1];
        double cnt  = sh_c[0] + sh_c[1];
        double mean = s / cnt;
        double var  = (ss - s * s / cnt) / (cnt - 1.0);
        s_mean = (float)mean;
        s_istd = (float)(1.0 / sqrt(var));
    }
    __syncthreads();

    const float mean = s_mean;
    const float is   = s_istd;

    v.x = (mi.x == 1) ? (v.x - mean) * is : 0.f;
    v.y = (mi.y == 1) ? (v.y - mean) * is : 0.f;
    v.z = (mi.z == 1) ? (v.z - mean) * is : 0.f;
    v.w = (mi.w == 1) ? (v.w - mean) * is : 0.f;

    reinterpret_cast<float4*>(out)[e4] = v;
}

// ---------------------------------------------------------------------------
extern "C" void kernel_launch(void* const* d_in, const int* in_sizes, int n_in,
                              void* d_out, int out_size) {
    const float* x    = (const float*)d_in[0];
    const int*   mask = (const int*)d_in[1];
    float*       out  = (float*)d_out;

    dim3 g1(PB, B);
    pool_kernel<<<g1, 256>>>(x, mask, out);

    norm_kernel<<<(B * 3 * HW4) / 256, 256>>>(mask, out);
}